// round 1
// baseline (speedup 1.0000x reference)
#include <cuda_runtime.h>

#define NV 100000
#define NL 8

// P table: 3.2 MB, L2-resident during the gather kernels.
__device__ __align__(256) float g_P[NV * NL];

// ---------------------------------------------------------------------------
// Block reduction: warp shuffle + smem, valid in thread 0.
__device__ __forceinline__ float block_reduce(float v) {
    v += __shfl_xor_sync(0xffffffffu, v, 16);
    v += __shfl_xor_sync(0xffffffffu, v, 8);
    v += __shfl_xor_sync(0xffffffffu, v, 4);
    v += __shfl_xor_sync(0xffffffffu, v, 2);
    v += __shfl_xor_sync(0xffffffffu, v, 1);
    __shared__ float s[8];
    int w = threadIdx.x >> 5;
    if ((threadIdx.x & 31) == 0) s[w] = v;
    __syncthreads();
    if (threadIdx.x < 8) {
        v = s[threadIdx.x];
        v += __shfl_xor_sync(0xffu, v, 4);
        v += __shfl_xor_sync(0xffu, v, 2);
        v += __shfl_xor_sync(0xffu, v, 1);
    }
    return v;
}

// ---------------------------------------------------------------------------
// Init: out = 2*E + 8*T  (constant parts of the analytic collapse).
__global__ void init_out(float* out, float base) {
    if (threadIdx.x == 0 && blockIdx.x == 0) out[0] = base;
}

// ---------------------------------------------------------------------------
// Build P = softmax(full, axis=1).
// full[v] = fixed_params[p] if v == fixed_indices[p], else
//           trainable_params[v - (#fixed < v)].
// fixed_indices assumed sorted ascending (it is arange in this dataset;
// binary search keeps it general for any sorted unique set).
__global__ void build_P(const float* __restrict__ trainable,
                        const float* __restrict__ fixedp,
                        const int*   __restrict__ fidx,
                        int n_fixed) {
    int v = blockIdx.x * blockDim.x + threadIdx.x;
    if (v >= NV) return;
    int lo = 0, hi = n_fixed;
    while (lo < hi) {
        int mid = (lo + hi) >> 1;
        if (__ldg(&fidx[mid]) < v) lo = mid + 1; else hi = mid;
    }
    const float* src;
    if (lo < n_fixed && __ldg(&fidx[lo]) == v)
        src = fixedp + (size_t)lo * NL;
    else
        src = trainable + (size_t)(v - lo) * NL;

    float x[NL];
#pragma unroll
    for (int i = 0; i < NL; i++) x[i] = __ldg(&src[i]);
    float m = x[0];
#pragma unroll
    for (int i = 1; i < NL; i++) m = fmaxf(m, x[i]);
    float sum = 0.f;
#pragma unroll
    for (int i = 0; i < NL; i++) { x[i] = __expf(x[i] - m); sum += x[i]; }
    float inv = 1.f / sum;
    float4* dst = reinterpret_cast<float4*>(g_P + (size_t)v * NL);
    dst[0] = make_float4(x[0] * inv, x[1] * inv, x[2] * inv, x[3] * inv);
    dst[1] = make_float4(x[4] * inv, x[5] * inv, x[6] * inv, x[7] * inv);
}

// ---------------------------------------------------------------------------
// Edges: contribution per edge = -(p . q)   [weight already folded: 2 * -1/2]
__global__ void edge_kernel(const int2* __restrict__ edges, int E,
                            float* __restrict__ out) {
    int i = blockIdx.x * blockDim.x + threadIdx.x;
    float acc = 0.f;
    if (i < E) {
        int2 e = edges[i];
        const float4* p = reinterpret_cast<const float4*>(g_P + (size_t)e.x * NL);
        const float4* q = reinterpret_cast<const float4*>(g_P + (size_t)e.y * NL);
        float4 p0 = p[0], p1 = p[1];
        float4 q0 = q[0], q1 = q[1];
        float d = p0.x * q0.x + p0.y * q0.y + p0.z * q0.z + p0.w * q0.w
                + p1.x * q1.x + p1.y * q1.y + p1.z * q1.z + p1.w * q1.w;
        acc = -d;
    }
    float tot = block_reduce(acc);
    if (threadIdx.x == 0) atomicAdd(out, tot);
}

// ---------------------------------------------------------------------------
// Triangles: contribution = -4*(p.q + p.r + q.r) + (16/3)*sum_a p_a q_a r_a
__global__ void tri_kernel(const int* __restrict__ tris, int T,
                           float* __restrict__ out) {
    int i = blockIdx.x * blockDim.x + threadIdx.x;
    float acc = 0.f;
    if (i < T) {
        int a = __ldg(&tris[3 * i + 0]);
        int b = __ldg(&tris[3 * i + 1]);
        int c = __ldg(&tris[3 * i + 2]);
        const float4* pp = reinterpret_cast<const float4*>(g_P + (size_t)a * NL);
        const float4* qp = reinterpret_cast<const float4*>(g_P + (size_t)b * NL);
        const float4* rp = reinterpret_cast<const float4*>(g_P + (size_t)c * NL);
        float p[NL], q[NL], r[NL];
        *reinterpret_cast<float4*>(p)     = pp[0];
        *reinterpret_cast<float4*>(p + 4) = pp[1];
        *reinterpret_cast<float4*>(q)     = qp[0];
        *reinterpret_cast<float4*>(q + 4) = qp[1];
        *reinterpret_cast<float4*>(r)     = rp[0];
        *reinterpret_cast<float4*>(r + 4) = rp[1];
        float s = 0.f, C = 0.f;
#pragma unroll
        for (int t = 0; t < NL; t++) {
            float qr = q[t] * r[t];
            s = fmaf(p[t], q[t] + r[t], s) + qr;
            C = fmaf(p[t], qr, C);
        }
        acc = -4.f * s + (16.f / 3.f) * C;
    }
    float tot = block_reduce(acc);
    if (threadIdx.x == 0) atomicAdd(out, tot);
}

// ---------------------------------------------------------------------------
extern "C" void kernel_launch(void* const* d_in, const int* in_sizes, int n_in,
                              void* d_out, int out_size) {
    const float* trainable = (const float*)d_in[0];   // (NV-n_fixed, 8)
    const float* fixedp    = (const float*)d_in[1];   // (n_fixed, 8)
    const int*   fidx      = (const int*)  d_in[2];   // (n_fixed,)
    const int*   s1        = (const int*)  d_in[3];   // (E, 2)
    const int*   s2        = (const int*)  d_in[4];   // (T, 3)
    float* out = (float*)d_out;

    int n_fixed = in_sizes[2];
    int E = in_sizes[3] / 2;
    int T = in_sizes[4] / 3;

    float base = 2.0f * (float)E + 8.0f * (float)T;
    init_out<<<1, 32>>>(out, base);

    build_P<<<(NV + 255) / 256, 256>>>(trainable, fixedp, fidx, n_fixed);

    edge_kernel<<<(E + 255) / 256, 256>>>((const int2*)s1, E, out);
    tri_kernel<<<(T + 255) / 256, 256>>>(s2, T, out);
}

// round 2
// speedup vs baseline: 1.2713x; 1.2713x over previous
#include <cuda_runtime.h>
#include <cuda_fp16.h>

#define NV 100000
#define NL 8

// P table in fp16: 100k rows x 8 halves = 16 B/row -> one LDG.128 per gather.
// 1.6 MB total, fully L2-resident.
__device__ __align__(256) __half g_Ph[NV * NL];

// ---------------------------------------------------------------------------
__device__ __forceinline__ float block_reduce(float v) {
    v += __shfl_xor_sync(0xffffffffu, v, 16);
    v += __shfl_xor_sync(0xffffffffu, v, 8);
    v += __shfl_xor_sync(0xffffffffu, v, 4);
    v += __shfl_xor_sync(0xffffffffu, v, 2);
    v += __shfl_xor_sync(0xffffffffu, v, 1);
    __shared__ float s[8];
    int w = threadIdx.x >> 5;
    if ((threadIdx.x & 31) == 0) s[w] = v;
    __syncthreads();
    if (threadIdx.x < 8) {
        v = s[threadIdx.x];
        v += __shfl_xor_sync(0xffu, v, 4);
        v += __shfl_xor_sync(0xffu, v, 2);
        v += __shfl_xor_sync(0xffu, v, 1);
    }
    return v;
}

// Load one P row (8 halves, 16 B) as fp32 values.
__device__ __forceinline__ void load_row(int v, float* f) {
    uint4 u = *reinterpret_cast<const uint4*>(g_Ph + (size_t)v * NL);
    float2 a = __half22float2(*reinterpret_cast<__half2*>(&u.x));
    float2 b = __half22float2(*reinterpret_cast<__half2*>(&u.y));
    float2 c = __half22float2(*reinterpret_cast<__half2*>(&u.z));
    float2 d = __half22float2(*reinterpret_cast<__half2*>(&u.w));
    f[0] = a.x; f[1] = a.y; f[2] = b.x; f[3] = b.y;
    f[4] = c.x; f[5] = c.y; f[6] = d.x; f[7] = d.y;
}

// ---------------------------------------------------------------------------
// Build P = softmax(full, axis=1) in fp16; thread 0 also seeds out = 2E+8T.
__global__ void build_P(const float* __restrict__ trainable,
                        const float* __restrict__ fixedp,
                        const int*   __restrict__ fidx,
                        int n_fixed, float* __restrict__ out, float base) {
    int v = blockIdx.x * blockDim.x + threadIdx.x;
    if (v == 0) out[0] = base;
    if (v >= NV) return;
    // binary search in sorted fixed_indices
    int lo = 0, hi = n_fixed;
    while (lo < hi) {
        int mid = (lo + hi) >> 1;
        if (__ldg(&fidx[mid]) < v) lo = mid + 1; else hi = mid;
    }
    const float* src;
    if (lo < n_fixed && __ldg(&fidx[lo]) == v)
        src = fixedp + (size_t)lo * NL;
    else
        src = trainable + (size_t)(v - lo) * NL;

    float x[NL];
#pragma unroll
    for (int i = 0; i < NL; i++) x[i] = __ldg(&src[i]);
    float m = x[0];
#pragma unroll
    for (int i = 1; i < NL; i++) m = fmaxf(m, x[i]);
    float sum = 0.f;
#pragma unroll
    for (int i = 0; i < NL; i++) { x[i] = __expf(x[i] - m); sum += x[i]; }
    float inv = 1.f / sum;

    __half h[NL];
#pragma unroll
    for (int i = 0; i < NL; i++) h[i] = __float2half_rn(x[i] * inv);
    *reinterpret_cast<uint4*>(g_Ph + (size_t)v * NL) =
        *reinterpret_cast<uint4*>(h);
}

// ---------------------------------------------------------------------------
// Fused gather: blocks [0, eb) handle edges, blocks [eb, eb+tb) triangles.
//   edge contribution: -(p.q)
//   tri  contribution: -4*(p.q + p.r + q.r) + (16/3)*sum_a p_a q_a r_a
__global__ void gather_kernel(const int2* __restrict__ edges, int E,
                              const int*  __restrict__ tris,  int T,
                              int eb, float* __restrict__ out) {
    float acc = 0.f;
    if (blockIdx.x < eb) {
        int i = blockIdx.x * blockDim.x + threadIdx.x;
        if (i < E) {
            int2 e = __ldg(&edges[i]);
            float p[NL], q[NL];
            load_row(e.x, p);
            load_row(e.y, q);
            float d = 0.f;
#pragma unroll
            for (int t = 0; t < NL; t++) d = fmaf(p[t], q[t], d);
            acc = -d;
        }
    } else {
        int i = (blockIdx.x - eb) * blockDim.x + threadIdx.x;
        if (i < T) {
            int a = __ldg(&tris[3 * i + 0]);
            int b = __ldg(&tris[3 * i + 1]);
            int c = __ldg(&tris[3 * i + 2]);
            float p[NL], q[NL], r[NL];
            load_row(a, p);
            load_row(b, q);
            load_row(c, r);
            float s = 0.f, C = 0.f;
#pragma unroll
            for (int t = 0; t < NL; t++) {
                float qr = q[t] * r[t];
                s = fmaf(p[t], q[t] + r[t], s) + qr;
                C = fmaf(p[t], qr, C);
            }
            acc = fmaf(-4.f, s, (16.f / 3.f) * C);
        }
    }
    float tot = block_reduce(acc);
    if (threadIdx.x == 0) atomicAdd(out, tot);
}

// ---------------------------------------------------------------------------
extern "C" void kernel_launch(void* const* d_in, const int* in_sizes, int n_in,
                              void* d_out, int out_size) {
    const float* trainable = (const float*)d_in[0];   // (NV-n_fixed, 8)
    const float* fixedp    = (const float*)d_in[1];   // (n_fixed, 8)
    const int*   fidx      = (const int*)  d_in[2];   // (n_fixed,)
    const int*   s1        = (const int*)  d_in[3];   // (E, 2)
    const int*   s2        = (const int*)  d_in[4];   // (T, 3)
    float* out = (float*)d_out;

    int n_fixed = in_sizes[2];
    int E = in_sizes[3] / 2;
    int T = in_sizes[4] / 3;

    float base = 2.0f * (float)E + 8.0f * (float)T;

    build_P<<<(NV + 255) / 256, 256>>>(trainable, fixedp, fidx, n_fixed,
                                       out, base);

    int eb = (E + 255) / 256;
    int tb = (T + 255) / 256;
    gather_kernel<<<eb + tb, 256>>>((const int2*)s1, E, s2, T, eb, out);
}